// round 1
// baseline (speedup 1.0000x reference)
#include <cuda_runtime.h>
#include <math.h>

#define MTOK 8192
#define DMODEL 1024
#define NH 16
#define DK 64
#define HID 4096
#define SEQ 2048

// Scratch buffers (no allocation allowed -> __device__ globals)
__device__ float g_xn[MTOK * DMODEL];
__device__ float g_q[MTOK * DMODEL];
__device__ float g_k[MTOK * DMODEL];
__device__ float g_v[MTOK * DMODEL];
__device__ float g_attn[MTOK * DMODEL];
__device__ float g_h[MTOK * DMODEL];
__device__ float g_y[MTOK * DMODEL];
__device__ float g_hidden[MTOK * HID];

// ---------------------------------------------------------------------------
// RMSNorm: one block per row (1024 elems), 256 threads x float4
// ---------------------------------------------------------------------------
__global__ __launch_bounds__(256) void rmsnorm_kernel(
    const float* __restrict__ x, const float* __restrict__ scale,
    float* __restrict__ out) {
    int row = blockIdx.x;
    int tid = threadIdx.x;
    const float4* xr = (const float4*)(x + (long)row * DMODEL);
    float4 v = xr[tid];
    float ss = v.x * v.x + v.y * v.y + v.z * v.z + v.w * v.w;
#pragma unroll
    for (int w = 16; w; w >>= 1) ss += __shfl_xor_sync(0xffffffffu, ss, w);
    __shared__ float red[8];
    if ((tid & 31) == 0) red[tid >> 5] = ss;
    __syncthreads();
    float tot = 0.f;
#pragma unroll
    for (int i = 0; i < 8; i++) tot += red[i];
    float r = rsqrtf(tot * (1.0f / 1024.0f) + 1e-6f);
    float4 sc = ((const float4*)scale)[tid];
    float4 o;
    o.x = v.x * r * sc.x;
    o.y = v.y * r * sc.y;
    o.z = v.z * r * sc.z;
    o.w = v.w * r * sc.w;
    ((float4*)(out + (long)row * DMODEL))[tid] = o;
}

// ---------------------------------------------------------------------------
// LayerNorm (effective scale = 1 + scale_param), one block per row
// ---------------------------------------------------------------------------
__global__ __launch_bounds__(256) void layernorm_kernel(
    const float* __restrict__ x, const float* __restrict__ scale,
    const float* __restrict__ bias, float* __restrict__ out) {
    int row = blockIdx.x;
    int tid = threadIdx.x;
    const float4* xr = (const float4*)(x + (long)row * DMODEL);
    float4 v = xr[tid];
    float s = v.x + v.y + v.z + v.w;
    float sq = v.x * v.x + v.y * v.y + v.z * v.z + v.w * v.w;
#pragma unroll
    for (int w = 16; w; w >>= 1) {
        s += __shfl_xor_sync(0xffffffffu, s, w);
        sq += __shfl_xor_sync(0xffffffffu, sq, w);
    }
    __shared__ float rs[8], rq[8];
    if ((tid & 31) == 0) { rs[tid >> 5] = s; rq[tid >> 5] = sq; }
    __syncthreads();
    float S = 0.f, Q = 0.f;
#pragma unroll
    for (int i = 0; i < 8; i++) { S += rs[i]; Q += rq[i]; }
    float mean = S * (1.0f / 1024.0f);
    float var = Q * (1.0f / 1024.0f) - mean * mean;
    float r = rsqrtf(var + 1e-6f);
    float4 sc = ((const float4*)scale)[tid];
    float4 bi = ((const float4*)bias)[tid];
    float4 o;
    o.x = (v.x - mean) * r * (1.0f + sc.x) + bi.x;
    o.y = (v.y - mean) * r * (1.0f + sc.y) + bi.y;
    o.z = (v.z - mean) * r * (1.0f + sc.z) + bi.z;
    o.w = (v.w - mean) * r * (1.0f + sc.w) + bi.w;
    ((float4*)(out + (long)row * DMODEL))[tid] = o;
}

// ---------------------------------------------------------------------------
// NT SGEMM: C[m,n] = sum_k A[m,k]*B[n,k] + bias[n] (+res) (+relu)
// 128x128 block tile, K-tile 16, 256 threads, 8x8 microtile
// Requires M%128==0, N%128==0, K%16==0 (true for all uses here)
// ---------------------------------------------------------------------------
template <bool RELU, bool RES>
__global__ __launch_bounds__(256) void gemm_nt(
    const float* __restrict__ A, const float* __restrict__ B,
    const float* __restrict__ bias, const float* __restrict__ res,
    float* __restrict__ C, int M, int N, int K) {
    __shared__ float As[16][132];
    __shared__ float Bs[16][132];
    int tid = threadIdx.x;
    int row0 = blockIdx.y * 128, col0 = blockIdx.x * 128;
    int ty = tid >> 4, tx = tid & 15;
    int lr = tid >> 2, lc = (tid & 3) << 2;
    const float* Ag = A + (long)(row0 + lr) * K + lc;
    const float* Bg = B + (long)(col0 + lr) * K + lc;
    float acc[8][8] = {};
    for (int k0 = 0; k0 < K; k0 += 16) {
        float4 a0 = *(const float4*)(Ag + k0);
        float4 a1 = *(const float4*)(Ag + (long)64 * K + k0);
        float4 b0 = *(const float4*)(Bg + k0);
        float4 b1 = *(const float4*)(Bg + (long)64 * K + k0);
        __syncthreads();
        As[lc + 0][lr] = a0.x; As[lc + 1][lr] = a0.y;
        As[lc + 2][lr] = a0.z; As[lc + 3][lr] = a0.w;
        As[lc + 0][lr + 64] = a1.x; As[lc + 1][lr + 64] = a1.y;
        As[lc + 2][lr + 64] = a1.z; As[lc + 3][lr + 64] = a1.w;
        Bs[lc + 0][lr] = b0.x; Bs[lc + 1][lr] = b0.y;
        Bs[lc + 2][lr] = b0.z; Bs[lc + 3][lr] = b0.w;
        Bs[lc + 0][lr + 64] = b1.x; Bs[lc + 1][lr + 64] = b1.y;
        Bs[lc + 2][lr + 64] = b1.z; Bs[lc + 3][lr + 64] = b1.w;
        __syncthreads();
#pragma unroll
        for (int kk = 0; kk < 16; kk++) {
            float a[8], b[8];
            *(float4*)(a) = *(const float4*)&As[kk][ty * 8];
            *(float4*)(a + 4) = *(const float4*)&As[kk][ty * 8 + 4];
            *(float4*)(b) = *(const float4*)&Bs[kk][tx * 8];
            *(float4*)(b + 4) = *(const float4*)&Bs[kk][tx * 8 + 4];
#pragma unroll
            for (int i = 0; i < 8; i++)
#pragma unroll
                for (int j = 0; j < 8; j++) acc[i][j] += a[i] * b[j];
        }
    }
    float bb[8];
#pragma unroll
    for (int j = 0; j < 8; j++) bb[j] = bias[col0 + tx * 8 + j];
#pragma unroll
    for (int i = 0; i < 8; i++) {
        long ridx = (long)(row0 + ty * 8 + i) * N + col0 + tx * 8;
#pragma unroll
        for (int j = 0; j < 8; j += 4) {
            float4 val;
            val.x = acc[i][j + 0] + bb[j + 0];
            val.y = acc[i][j + 1] + bb[j + 1];
            val.z = acc[i][j + 2] + bb[j + 2];
            val.w = acc[i][j + 3] + bb[j + 3];
            if (RELU) {
                val.x = fmaxf(val.x, 0.f); val.y = fmaxf(val.y, 0.f);
                val.z = fmaxf(val.z, 0.f); val.w = fmaxf(val.w, 0.f);
            }
            if (RES) {
                float4 r4 = *(const float4*)&res[ridx + j];
                val.x += r4.x; val.y += r4.y; val.z += r4.z; val.w += r4.w;
            }
            *(float4*)&C[ridx + j] = val;
        }
    }
}

// ---------------------------------------------------------------------------
// Flash attention: grid (S/64, B*H), 256 threads, 64x64 tiles, online softmax
// q/k/v layout: [B, S, H*DK] (GEMM output), head h at column offset h*64
// ---------------------------------------------------------------------------
__global__ __launch_bounds__(256) void attention_kernel(
    const float* __restrict__ q, const float* __restrict__ k,
    const float* __restrict__ v, const float* __restrict__ mask,
    const float* __restrict__ pds, float* __restrict__ out) {
    __shared__ float Qs[64][68];   // [row][d], padded for alignment
    __shared__ float Ks[64][64];   // [d][col]  (transposed)
    __shared__ float Vs[64][64];   // [key][d]
    __shared__ float Ps[64][68];   // [row][key]
    __shared__ float sscale[64];

    int tid = threadIdx.x;
    int bh = blockIdx.y;
    int b = bh >> 4, h = bh & 15;
    int q0 = blockIdx.x * 64;
    long base = (long)b * SEQ * DMODEL + h * DK;
    const float* qb = q + base;
    const float* kb = k + base;
    const float* vb = v + base;

    if (tid < 64) sscale[tid] = 0.18033688f * log1pf(__expf(pds[tid]));
    __syncthreads();

    {   // load scaled Q tile
        int lr = tid >> 2, ld = (tid & 3) << 4;
        const float* src = qb + (long)(q0 + lr) * DMODEL + ld;
#pragma unroll
        for (int t = 0; t < 16; t += 4) {
            float4 val = *(const float4*)(src + t);
            Qs[lr][ld + t + 0] = val.x * sscale[ld + t + 0];
            Qs[lr][ld + t + 1] = val.y * sscale[ld + t + 1];
            Qs[lr][ld + t + 2] = val.z * sscale[ld + t + 2];
            Qs[lr][ld + t + 3] = val.w * sscale[ld + t + 3];
        }
    }

    int ty = tid >> 4, tx = tid & 15;
    int r0 = ty << 2, c0 = tx << 2;
    float o[4][4] = {};
    float m[4], l[4] = {};
#pragma unroll
    for (int i = 0; i < 4; i++) m[i] = -1e30f;

    for (int k0 = 0; k0 < SEQ; k0 += 64) {
        __syncthreads();   // prior P.V reads done before overwriting K/V
        {   // load K (transposed) and V tiles
            int lr = tid >> 2, ld = (tid & 3) << 4;
            const float* ksrc = kb + (long)(k0 + lr) * DMODEL + ld;
            const float* vsrc = vb + (long)(k0 + lr) * DMODEL + ld;
#pragma unroll
            for (int t = 0; t < 16; t += 4) {
                float4 kv = *(const float4*)(ksrc + t);
                Ks[ld + t + 0][lr] = kv.x;
                Ks[ld + t + 1][lr] = kv.y;
                Ks[ld + t + 2][lr] = kv.z;
                Ks[ld + t + 3][lr] = kv.w;
                *(float4*)&Vs[lr][ld + t] = *(const float4*)(vsrc + t);
            }
        }
        __syncthreads();

        // scores: s[i][j] = Q[r0+i][:] . K[c0+j][:]
        float s[4][4] = {};
#pragma unroll
        for (int kk = 0; kk < 64; kk += 4) {
            float4 qv[4];
#pragma unroll
            for (int i = 0; i < 4; i++) qv[i] = *(const float4*)&Qs[r0 + i][kk];
#pragma unroll
            for (int t = 0; t < 4; t++) {
                float4 kv = *(const float4*)&Ks[kk + t][c0];
#pragma unroll
                for (int i = 0; i < 4; i++) {
                    float qi = (t == 0) ? qv[i].x : (t == 1) ? qv[i].y
                             : (t == 2) ? qv[i].z : qv[i].w;
                    s[i][0] += qi * kv.x;
                    s[i][1] += qi * kv.y;
                    s[i][2] += qi * kv.z;
                    s[i][3] += qi * kv.w;
                }
            }
        }

        // mask + online softmax (row groups = 16 contiguous lanes of a half-warp)
#pragma unroll
        for (int i = 0; i < 4; i++) {
            float4 mk = *(const float4*)&mask[(long)(q0 + r0 + i) * SEQ + k0 + c0];
            s[i][0] += mk.x; s[i][1] += mk.y; s[i][2] += mk.z; s[i][3] += mk.w;
            float tm = fmaxf(fmaxf(s[i][0], s[i][1]), fmaxf(s[i][2], s[i][3]));
#pragma unroll
            for (int w = 8; w; w >>= 1)
                tm = fmaxf(tm, __shfl_xor_sync(0xffffffffu, tm, w));
            float nm = fmaxf(m[i], tm);
            float corr = __expf(m[i] - nm);
            float ts = 0.f;
#pragma unroll
            for (int j = 0; j < 4; j++) {
                float p = __expf(s[i][j] - nm);
                s[i][j] = p;
                ts += p;
            }
#pragma unroll
            for (int w = 8; w; w >>= 1)
                ts += __shfl_xor_sync(0xffffffffu, ts, w);
            l[i] = l[i] * corr + ts;
            m[i] = nm;
            o[i][0] *= corr; o[i][1] *= corr; o[i][2] *= corr; o[i][3] *= corr;
            *(float4*)&Ps[r0 + i][c0] = make_float4(s[i][0], s[i][1], s[i][2], s[i][3]);
        }
        __syncthreads();

        // O += P . V
#pragma unroll
        for (int j0 = 0; j0 < 64; j0 += 4) {
            float4 pv[4];
#pragma unroll
            for (int i = 0; i < 4; i++) pv[i] = *(const float4*)&Ps[r0 + i][j0];
#pragma unroll
            for (int t = 0; t < 4; t++) {
                float4 vv = *(const float4*)&Vs[j0 + t][c0];
#pragma unroll
                for (int i = 0; i < 4; i++) {
                    float pi = (t == 0) ? pv[i].x : (t == 1) ? pv[i].y
                             : (t == 2) ? pv[i].z : pv[i].w;
                    o[i][0] += pi * vv.x;
                    o[i][1] += pi * vv.y;
                    o[i][2] += pi * vv.z;
                    o[i][3] += pi * vv.w;
                }
            }
        }
    }

#pragma unroll
    for (int i = 0; i < 4; i++) {
        float inv = 1.0f / l[i];
        float4 ov = make_float4(o[i][0] * inv, o[i][1] * inv,
                                o[i][2] * inv, o[i][3] * inv);
        *(float4*)&out[base + (long)(q0 + r0 + i) * DMODEL + c0] = ov;
    }
}

// ---------------------------------------------------------------------------
extern "C" void kernel_launch(void* const* d_in, const int* in_sizes, int n_in,
                              void* d_out, int out_size) {
    const float* inputs   = (const float*)d_in[0];
    const float* mask     = (const float*)d_in[1];
    const float* rmsscale = (const float*)d_in[2];
    const float* Wq = (const float*)d_in[3];
    const float* bq = (const float*)d_in[4];
    const float* Wk = (const float*)d_in[5];
    const float* bk = (const float*)d_in[6];
    const float* Wv = (const float*)d_in[7];
    const float* bv = (const float*)d_in[8];
    const float* pds = (const float*)d_in[9];
    const float* Wpost = (const float*)d_in[10];
    const float* bpost = (const float*)d_in[11];
    const float* ln_scale = (const float*)d_in[12];
    const float* ln_bias  = (const float*)d_in[13];
    const float* W1 = (const float*)d_in[14];
    const float* b1 = (const float*)d_in[15];
    const float* W2 = (const float*)d_in[16];
    const float* b2 = (const float*)d_in[17];
    float* out = (float*)d_out;

    float *xn, *q, *k, *v, *attn, *h, *y, *hidden;
    cudaGetSymbolAddress((void**)&xn, g_xn);
    cudaGetSymbolAddress((void**)&q, g_q);
    cudaGetSymbolAddress((void**)&k, g_k);
    cudaGetSymbolAddress((void**)&v, g_v);
    cudaGetSymbolAddress((void**)&attn, g_attn);
    cudaGetSymbolAddress((void**)&h, g_h);
    cudaGetSymbolAddress((void**)&y, g_y);
    cudaGetSymbolAddress((void**)&hidden, g_hidden);

    dim3 g8(8, 64), g32(32, 64);

    rmsnorm_kernel<<<MTOK, 256>>>(inputs, rmsscale, xn);
    gemm_nt<false, false><<<g8, 256>>>(xn, Wq, bq, nullptr, q, MTOK, DMODEL, DMODEL);
    gemm_nt<false, false><<<g8, 256>>>(xn, Wk, bk, nullptr, k, MTOK, DMODEL, DMODEL);
    gemm_nt<false, false><<<g8, 256>>>(xn, Wv, bv, nullptr, v, MTOK, DMODEL, DMODEL);
    attention_kernel<<<dim3(32, 64), 256>>>(q, k, v, mask, pds, attn);
    gemm_nt<false, true><<<g8, 256>>>(attn, Wpost, bpost, inputs, h, MTOK, DMODEL, DMODEL);
    layernorm_kernel<<<MTOK, 256>>>(h, ln_scale, ln_bias, y);
    gemm_nt<true, false><<<g32, 256>>>(y, W1, b1, nullptr, hidden, MTOK, HID, DMODEL);
    gemm_nt<false, true><<<g8, 256>>>(hidden, W2, b2, h, out, MTOK, DMODEL, HID);
}

// round 3
// speedup vs baseline: 1.5275x; 1.5275x over previous
#include <cuda_runtime.h>
#include <cuda_bf16.h>
#include <cstdint>
#include <math.h>

#define MTOK 8192
#define DMODEL 1024
#define NH 16
#define DK 64
#define HID 4096
#define SEQ 2048
#define KP1 (3 * DMODEL)   /* 3072  */
#define KP2 (3 * HID)      /* 12288 */

// ---------------------------------------------------------------------------
// Scratch (__device__ globals; allocation is forbidden)
// ---------------------------------------------------------------------------
__device__ __nv_bfloat16 g_xn_s[MTOK * KP1];          // rmsnorm out, split
__device__ float         g_q[MTOK * DMODEL];
__device__ float         g_k[MTOK * DMODEL];
__device__ float         g_v[MTOK * DMODEL];
__device__ __nv_bfloat16 g_attn_s[MTOK * KP1];        // attention out, split
__device__ float         g_h[MTOK * DMODEL];          // residual 1
__device__ __nv_bfloat16 g_y_s[MTOK * KP1];           // layernorm out, split
__device__ __nv_bfloat16 g_hid_s[(long)MTOK * KP2];   // relu(ffn1) out, split
__device__ __nv_bfloat16 g_wq[DMODEL * KP1];
__device__ __nv_bfloat16 g_wk[DMODEL * KP1];
__device__ __nv_bfloat16 g_wv[DMODEL * KP1];
__device__ __nv_bfloat16 g_wpost[DMODEL * KP1];
__device__ __nv_bfloat16 g_w1[HID * KP1];
__device__ __nv_bfloat16 g_w2[DMODEL * KP2];

// ---------------------------------------------------------------------------
// Helpers
// ---------------------------------------------------------------------------
__device__ __forceinline__ uint32_t s2u(const void* p) {
    uint32_t a;
    asm("{ .reg .u64 t; cvta.to.shared.u64 t, %1; cvt.u32.u64 %0, t; }"
        : "=r"(a) : "l"(p));
    return a;
}
#define SW128(o) ((o) ^ (((o) >> 3) & 0x70))

__device__ __forceinline__ void split2(float f, __nv_bfloat16& h, __nv_bfloat16& l) {
    h = __float2bfloat16(f);
    l = __float2bfloat16(f - __bfloat162float(h));
}
__device__ __forceinline__ __nv_bfloat162 mk2(__nv_bfloat16 a, __nv_bfloat16 b) {
    __nv_bfloat162 r; r.x = a; r.y = b; return r;
}

// ---------------------------------------------------------------------------
// Weight split: W fp32 [R,K] -> bf16 [R,3K] as [hi, hi, lo]
// ---------------------------------------------------------------------------
__global__ __launch_bounds__(256) void split_w_kernel(
    const float* __restrict__ W, __nv_bfloat16* __restrict__ out,
    int K, long total4) {
    long idx = blockIdx.x * 256L + threadIdx.x;
    if (idx >= total4) return;
    int kq = K >> 2;
    long m = idx / kq;
    int kk = (int)(idx % kq) << 2;
    float4 v = *(const float4*)(W + m * K + kk);
    __nv_bfloat16 h0, l0, h1, l1, h2, l2, h3, l3;
    split2(v.x, h0, l0); split2(v.y, h1, l1);
    split2(v.z, h2, l2); split2(v.w, h3, l3);
    __nv_bfloat16* o = out + m * (long)(3 * K) + kk;
    *(__nv_bfloat162*)(o) = mk2(h0, h1);
    *(__nv_bfloat162*)(o + 2) = mk2(h2, h3);
    *(__nv_bfloat162*)(o + K) = mk2(h0, h1);
    *(__nv_bfloat162*)(o + K + 2) = mk2(h2, h3);
    *(__nv_bfloat162*)(o + 2 * K) = mk2(l0, l1);
    *(__nv_bfloat162*)(o + 2 * K + 2) = mk2(l2, l3);
}

// ---------------------------------------------------------------------------
// RMSNorm -> split bf16 [M, 3K] as [hi, lo, hi]
// ---------------------------------------------------------------------------
__global__ __launch_bounds__(256) void rmsnorm_split_kernel(
    const float* __restrict__ x, const float* __restrict__ scale,
    __nv_bfloat16* __restrict__ out) {
    int row = blockIdx.x;
    int tid = threadIdx.x;
    float4 v = ((const float4*)(x + (long)row * DMODEL))[tid];
    float ss = v.x * v.x + v.y * v.y + v.z * v.z + v.w * v.w;
#pragma unroll
    for (int w = 16; w; w >>= 1) ss += __shfl_xor_sync(0xffffffffu, ss, w);
    __shared__ float red[8];
    if ((tid & 31) == 0) red[tid >> 5] = ss;
    __syncthreads();
    float tot = 0.f;
#pragma unroll
    for (int i = 0; i < 8; i++) tot += red[i];
    float r = rsqrtf(tot * (1.0f / 1024.0f) + 1e-6f);
    float4 sc = ((const float4*)scale)[tid];
    float f0 = v.x * r * sc.x, f1 = v.y * r * sc.y;
    float f2 = v.z * r * sc.z, f3 = v.w * r * sc.w;
    __nv_bfloat16 h0, l0, h1, l1, h2, l2, h3, l3;
    split2(f0, h0, l0); split2(f1, h1, l1);
    split2(f2, h2, l2); split2(f3, h3, l3);
    __nv_bfloat16* o = out + (long)row * KP1 + tid * 4;
    *(__nv_bfloat162*)(o) = mk2(h0, h1);
    *(__nv_bfloat162*)(o + 2) = mk2(h2, h3);
    *(__nv_bfloat162*)(o + DMODEL) = mk2(l0, l1);
    *(__nv_bfloat162*)(o + DMODEL + 2) = mk2(l2, l3);
    *(__nv_bfloat162*)(o + 2 * DMODEL) = mk2(h0, h1);
    *(__nv_bfloat162*)(o + 2 * DMODEL + 2) = mk2(h2, h3);
}

// ---------------------------------------------------------------------------
// LayerNorm -> split bf16 [M, 3K]
// ---------------------------------------------------------------------------
__global__ __launch_bounds__(256) void layernorm_split_kernel(
    const float* __restrict__ x, const float* __restrict__ scale,
    const float* __restrict__ bias, __nv_bfloat16* __restrict__ out) {
    int row = blockIdx.x;
    int tid = threadIdx.x;
    float4 v = ((const float4*)(x + (long)row * DMODEL))[tid];
    float s = v.x + v.y + v.z + v.w;
    float sq = v.x * v.x + v.y * v.y + v.z * v.z + v.w * v.w;
#pragma unroll
    for (int w = 16; w; w >>= 1) {
        s += __shfl_xor_sync(0xffffffffu, s, w);
        sq += __shfl_xor_sync(0xffffffffu, sq, w);
    }
    __shared__ float rs[8], rq[8];
    if ((tid & 31) == 0) { rs[tid >> 5] = s; rq[tid >> 5] = sq; }
    __syncthreads();
    float S = 0.f, Q = 0.f;
#pragma unroll
    for (int i = 0; i < 8; i++) { S += rs[i]; Q += rq[i]; }
    float mean = S * (1.0f / 1024.0f);
    float var = Q * (1.0f / 1024.0f) - mean * mean;
    float r = rsqrtf(var + 1e-6f);
    float4 sc = ((const float4*)scale)[tid];
    float4 bi = ((const float4*)bias)[tid];
    float f0 = (v.x - mean) * r * (1.0f + sc.x) + bi.x;
    float f1 = (v.y - mean) * r * (1.0f + sc.y) + bi.y;
    float f2 = (v.z - mean) * r * (1.0f + sc.z) + bi.z;
    float f3 = (v.w - mean) * r * (1.0f + sc.w) + bi.w;
    __nv_bfloat16 h0, l0, h1, l1, h2, l2, h3, l3;
    split2(f0, h0, l0); split2(f1, h1, l1);
    split2(f2, h2, l2); split2(f3, h3, l3);
    __nv_bfloat16* o = out + (long)row * KP1 + tid * 4;
    *(__nv_bfloat162*)(o) = mk2(h0, h1);
    *(__nv_bfloat162*)(o + 2) = mk2(h2, h3);
    *(__nv_bfloat162*)(o + DMODEL) = mk2(l0, l1);
    *(__nv_bfloat162*)(o + DMODEL + 2) = mk2(l2, l3);
    *(__nv_bfloat162*)(o + 2 * DMODEL) = mk2(h0, h1);
    *(__nv_bfloat162*)(o + 2 * DMODEL + 2) = mk2(h2, h3);
}

// ---------------------------------------------------------------------------
// mma.sync bf16 GEMM: C[m,n] = sum_k A[m,k]*B[n,k] (+bias)(+relu)(+res)
// A [M,Kp], B [N,Kp] bf16 row-major. 128x128 CTA tile, BK=64, cp.async
// double-buffered, 8 warps (2m x 4n), warp tile 64x32 via m16n8k16.
// SPLIT: write bf16 [hi,lo,hi] at pitch 3N instead of fp32.
// ---------------------------------------------------------------------------
template <bool RELU, bool RES, bool SPLIT>
__global__ void __launch_bounds__(256, 2) gemm_mma(
    const __nv_bfloat16* __restrict__ A, const __nv_bfloat16* __restrict__ Bw,
    const float* __restrict__ bias, const float* __restrict__ res,
    float* __restrict__ Cf, __nv_bfloat16* __restrict__ Cs, int N, int Kp) {
    extern __shared__ char smem[];
    uint32_t sbase = s2u(smem);
    int tid = threadIdx.x;
    int wid = tid >> 5, lane = tid & 31;
    int wm = (wid & 1) * 64;
    int wn = (wid >> 1) * 32;
    long row0 = (long)blockIdx.y * 128, col0 = (long)blockIdx.x * 128;
    const __nv_bfloat16* Ab = A + row0 * (long)Kp;
    const __nv_bfloat16* Bb = Bw + col0 * (long)Kp;

    // cp.async mapping: 2 threads per 128B row, 4x16B chunks each
    int ldr = tid >> 1;
    int ldc = (tid & 1) * 4;

    auto issue = [&](int c, int s) {
        long kc = (long)c << 6;
        uint32_t abase = sbase + (uint32_t)s * 32768u;
        uint32_t bbase = abase + 16384u;
        const __nv_bfloat16* ag = Ab + (long)ldr * Kp + kc + ldc * 8;
        const __nv_bfloat16* bg = Bb + (long)ldr * Kp + kc + ldc * 8;
#pragma unroll
        for (int i = 0; i < 4; i++) {
            uint32_t off = SW128((uint32_t)(ldr * 128 + (ldc + i) * 16));
            asm volatile("cp.async.cg.shared.global [%0], [%1], 16;"
                         :: "r"(abase + off), "l"(ag + i * 8) : "memory");
            asm volatile("cp.async.cg.shared.global [%0], [%1], 16;"
                         :: "r"(bbase + off), "l"(bg + i * 8) : "memory");
        }
        asm volatile("cp.async.commit_group;" ::: "memory");
    };

    float acc[4][4][4] = {};
    const int C = Kp >> 6;

    issue(0, 0);
    for (int c = 0; c < C; c++) {
        if (c + 1 < C) {
            issue(c + 1, (c + 1) & 1);
            asm volatile("cp.async.wait_group 1;" ::: "memory");
        } else {
            asm volatile("cp.async.wait_group 0;" ::: "memory");
        }
        __syncthreads();
        uint32_t abase = sbase + (uint32_t)(c & 1) * 32768u;
        uint32_t bbase = abase + 16384u;
#pragma unroll
        for (int ks = 0; ks < 4; ks++) {
            uint32_t a[4][4], b[2][4];
#pragma unroll
            for (int mt = 0; mt < 4; mt++) {
                int r = wm + mt * 16 + (lane & 15);
                uint32_t off = SW128((uint32_t)(r * 128 + ks * 32 + ((lane >> 4) << 4)));
                asm volatile(
                    "ldmatrix.sync.aligned.m8n8.x4.shared.b16 {%0,%1,%2,%3}, [%4];"
                    : "=r"(a[mt][0]), "=r"(a[mt][1]), "=r"(a[mt][2]), "=r"(a[mt][3])
                    : "r"(abase + off));
            }
#pragma unroll
            for (int nt2 = 0; nt2 < 2; nt2++) {
                int nr = wn + nt2 * 16 + (lane & 7) + ((lane >> 4) << 3);
                uint32_t off = SW128(
                    (uint32_t)(nr * 128 + ks * 32 + (((lane >> 3) & 1) << 4)));
                asm volatile(
                    "ldmatrix.sync.aligned.m8n8.x4.shared.b16 {%0,%1,%2,%3}, [%4];"
                    : "=r"(b[nt2][0]), "=r"(b[nt2][1]), "=r"(b[nt2][2]), "=r"(b[nt2][3])
                    : "r"(bbase + off));
            }
#pragma unroll
            for (int mt = 0; mt < 4; mt++)
#pragma unroll
                for (int nt = 0; nt < 4; nt++) {
                    uint32_t b0 = b[nt >> 1][(nt & 1) * 2];
                    uint32_t b1 = b[nt >> 1][(nt & 1) * 2 + 1];
                    asm volatile(
                        "mma.sync.aligned.m16n8k16.row.col.f32.bf16.bf16.f32 "
                        "{%0,%1,%2,%3}, {%4,%5,%6,%7}, {%8,%9}, {%0,%1,%2,%3};"
                        : "+f"(acc[mt][nt][0]), "+f"(acc[mt][nt][1]),
                          "+f"(acc[mt][nt][2]), "+f"(acc[mt][nt][3])
                        : "r"(a[mt][0]), "r"(a[mt][1]), "r"(a[mt][2]),
                          "r"(a[mt][3]), "r"(b0), "r"(b1));
                }
        }
        __syncthreads();
    }

    // Epilogue: lane t owns rows (t/4, t/4+8), cols (t%4)*2,+1 per 16x8 tile
    int tq = lane >> 2, tr = lane & 3;
#pragma unroll
    for (int mt = 0; mt < 4; mt++) {
#pragma unroll
        for (int half = 0; half < 2; half++) {
            long row = row0 + wm + mt * 16 + tq + half * 8;
#pragma unroll
            for (int nt = 0; nt < 4; nt++) {
                int col = (int)col0 + wn + nt * 8 + tr * 2;
                float v0 = acc[mt][nt][half * 2 + 0] + bias[col];
                float v1 = acc[mt][nt][half * 2 + 1] + bias[col + 1];
                if (RELU) { v0 = fmaxf(v0, 0.f); v1 = fmaxf(v1, 0.f); }
                if (SPLIT) {
                    __nv_bfloat16 h0, l0, h1, l1;
                    split2(v0, h0, l0); split2(v1, h1, l1);
                    __nv_bfloat16* o = Cs + row * (long)(3 * N) + col;
                    *(__nv_bfloat162*)(o) = mk2(h0, h1);
                    *(__nv_bfloat162*)(o + N) = mk2(l0, l1);
                    *(__nv_bfloat162*)(o + 2 * N) = mk2(h0, h1);
                } else {
                    long idx = row * (long)N + col;
                    if (RES) {
                        float2 r2 = *(const float2*)(res + idx);
                        v0 += r2.x; v1 += r2.y;
                    }
                    float2 o2; o2.x = v0; o2.y = v1;
                    *(float2*)(Cf + idx) = o2;
                }
            }
        }
    }
}

// ---------------------------------------------------------------------------
// Flash attention (fp32), epilogue writes split bf16 [B,S,3*DMODEL]
// ---------------------------------------------------------------------------
__global__ __launch_bounds__(256) void attention_kernel(
    const float* __restrict__ q, const float* __restrict__ k,
    const float* __restrict__ v, const float* __restrict__ mask,
    const float* __restrict__ pds, __nv_bfloat16* __restrict__ out) {
    __shared__ float Qs[64][68];
    __shared__ float Ks[64][64];
    __shared__ float Vs[64][64];
    __shared__ float Ps[64][68];
    __shared__ float sscale[64];

    int tid = threadIdx.x;
    int bh = blockIdx.y;
    int b = bh >> 4, h = bh & 15;
    int q0 = blockIdx.x * 64;
    long base = (long)b * SEQ * DMODEL + h * DK;
    const float* qb = q + base;
    const float* kb = k + base;
    const float* vb = v + base;

    if (tid < 64) sscale[tid] = 0.18033688f * log1pf(__expf(pds[tid]));
    __syncthreads();

    {
        int lr = tid >> 2, ld = (tid & 3) << 4;
        const float* src = qb + (long)(q0 + lr) * DMODEL + ld;
#pragma unroll
        for (int t = 0; t < 16; t += 4) {
            float4 val = *(const float4*)(src + t);
            Qs[lr][ld + t + 0] = val.x * sscale[ld + t + 0];
            Qs[lr][ld + t + 1] = val.y * sscale[ld + t + 1];
            Qs[lr][ld + t + 2] = val.z * sscale[ld + t + 2];
            Qs[lr][ld + t + 3] = val.w * sscale[ld + t + 3];
        }
    }

    int ty = tid >> 4, tx = tid & 15;
    int r0 = ty << 2, c0 = tx << 2;
    float o[4][4] = {};
    float m[4], l[4] = {};
#pragma unroll
    for (int i = 0; i < 4; i++) m[i] = -1e30f;

    for (int k0 = 0; k0 < SEQ; k0 += 64) {
        __syncthreads();
        {
            int lr = tid >> 2, ld = (tid & 3) << 4;
            const float* ksrc = kb + (long)(k0 + lr) * DMODEL + ld;
            const float* vsrc = vb + (long)(k0 + lr) * DMODEL + ld;
#pragma unroll
            for (int t = 0; t < 16; t += 4) {
                float4 kv = *(const float4*)(ksrc + t);
                Ks[ld + t + 0][lr] = kv.x;
                Ks[ld + t + 1][lr] = kv.y;
                Ks[ld + t + 2][lr] = kv.z;
                Ks[ld + t + 3][lr] = kv.w;
                *(float4*)&Vs[lr][ld + t] = *(const float4*)(vsrc + t);
            }
        }
        __syncthreads();

        float s[4][4] = {};
#pragma unroll
        for (int kk = 0; kk < 64; kk += 4) {
            float4 qv[4];
#pragma unroll
            for (int i = 0; i < 4; i++) qv[i] = *(const float4*)&Qs[r0 + i][kk];
#pragma unroll
            for (int t = 0; t < 4; t++) {
                float4 kv = *(const float4*)&Ks[kk + t][c0];
#pragma unroll
                for (int i = 0; i < 4; i++) {
                    float qi = (t == 0) ? qv[i].x : (t == 1) ? qv[i].y
                             : (t == 2) ? qv[i].z : qv[i].w;
                    s[i][0] += qi * kv.x;
                    s[i][1] += qi * kv.y;
                    s[i][2] += qi * kv.z;
                    s[i][3] += qi * kv.w;
                }
            }
        }

#pragma unroll
        for (int i = 0; i < 4; i++) {
            float4 mk = *(const float4*)&mask[(long)(q0 + r0 + i) * SEQ + k0 + c0];
            s[i][0] += mk.x; s[i][1] += mk.y; s[i][2] += mk.z; s[i][3] += mk.w;
            float tm = fmaxf(fmaxf(s[i][0], s[i][1]), fmaxf(s[i][2], s[i][3]));
#pragma unroll
            for (int w = 8; w; w >>= 1)
                tm = fmaxf(tm, __shfl_xor_sync(0xffffffffu, tm, w));
            float nm = fmaxf(m[i], tm);
            float corr = __expf(m[i] - nm);
            float ts = 0.f;
#pragma unroll
            for (int j = 0; j < 4; j++) {
                float p = __expf(s[i][j] - nm);
                s[i][j] = p;
                ts += p;
            }
#pragma unroll
            for (int w = 8; w; w >>= 1)
                ts += __shfl_xor_sync(0xffffffffu, ts, w);
            l[i] = l[i] * corr + ts;
            m[i] = nm;
            o[i][0] *= corr; o[i][1] *= corr; o[i][2] *= corr; o[i][3] *= corr;
            *(float4*)&Ps[r0 + i][c0] = make_float4(s[i][0], s[i][1], s[i][2], s[i][3]);
        }
        __syncthreads();

#pragma unroll
        for (int j0 = 0; j0 < 64; j0 += 4) {
            float4 pv[4];
#pragma unroll
            for (int i = 0; i < 4; i++) pv[i] = *(const float4*)&Ps[r0 + i][j0];
#pragma unroll
            for (int t = 0; t < 4; t++) {
                float4 vv = *(const float4*)&Vs[j0 + t][c0];
#pragma unroll
                for (int i = 0; i < 4; i++) {
                    float pi = (t == 0) ? pv[i].x : (t == 1) ? pv[i].y
                             : (t == 2) ? pv[i].z : pv[i].w;
                    o[i][0] += pi * vv.x;
                    o[i][1] += pi * vv.y;
                    o[i][2] += pi * vv.z;
                    o[i][3] += pi * vv.w;
                }
            }
        }
    }

    long base3 = (long)b * SEQ * KP1 + h * DK;
#pragma unroll
    for (int i = 0; i < 4; i++) {
        float inv = 1.0f / l[i];
        float f0 = o[i][0] * inv, f1 = o[i][1] * inv;
        float f2 = o[i][2] * inv, f3 = o[i][3] * inv;
        __nv_bfloat16 h0, l0b, h1, l1b, h2, l2b, h3, l3b;
        split2(f0, h0, l0b); split2(f1, h1, l1b);
        split2(f2, h2, l2b); split2(f3, h3, l3b);
        __nv_bfloat16* op = out + base3 + (long)(q0 + r0 + i) * KP1 + c0;
        *(__nv_bfloat162*)(op) = mk2(h0, h1);
        *(__nv_bfloat162*)(op + 2) = mk2(h2, h3);
        *(__nv_bfloat162*)(op + DMODEL) = mk2(l0b, l1b);
        *(__nv_bfloat162*)(op + DMODEL + 2) = mk2(l2b, l3b);
        *(__nv_bfloat162*)(op + 2 * DMODEL) = mk2(h0, h1);
        *(__nv_bfloat162*)(op + 2 * DMODEL + 2) = mk2(h2, h3);
    }
}

// ---------------------------------------------------------------------------
extern "C" void kernel_launch(void* const* d_in, const int* in_sizes, int n_in,
                              void* d_out, int out_size) {
    const float* inputs   = (const float*)d_in[0];
    const float* mask     = (const float*)d_in[1];
    const float* rmsscale = (const float*)d_in[2];
    const float* Wq = (const float*)d_in[3];
    const float* bq = (const float*)d_in[4];
    const float* Wk = (const float*)d_in[5];
    const float* bk = (const float*)d_in[6];
    const float* Wv = (const float*)d_in[7];
    const float* bv = (const float*)d_in[8];
    const float* pds = (const float*)d_in[9];
    const float* Wpost = (const float*)d_in[10];
    const float* bpost = (const float*)d_in[11];
    const float* ln_scale = (const float*)d_in[12];
    const float* ln_bias  = (const float*)d_in[13];
    const float* W1 = (const float*)d_in[14];
    const float* b1 = (const float*)d_in[15];
    const float* W2 = (const float*)d_in[16];
    const float* b2 = (const float*)d_in[17];
    float* out = (float*)d_out;

    __nv_bfloat16 *xn_s, *attn_s, *y_s, *hid_s, *wq, *wk, *wv, *wpost, *w1, *w2;
    float *q, *k, *v, *h;
    cudaGetSymbolAddress((void**)&xn_s, g_xn_s);
    cudaGetSymbolAddress((void**)&q, g_q);
    cudaGetSymbolAddress((void**)&k, g_k);
    cudaGetSymbolAddress((void**)&v, g_v);
    cudaGetSymbolAddress((void**)&attn_s, g_attn_s);
    cudaGetSymbolAddress((void**)&h, g_h);
    cudaGetSymbolAddress((void**)&y_s, g_y_s);
    cudaGetSymbolAddress((void**)&hid_s, g_hid_s);
    cudaGetSymbolAddress((void**)&wq, g_wq);
    cudaGetSymbolAddress((void**)&wk, g_wk);
    cudaGetSymbolAddress((void**)&wv, g_wv);
    cudaGetSymbolAddress((void**)&wpost, g_wpost);
    cudaGetSymbolAddress((void**)&w1, g_w1);
    cudaGetSymbolAddress((void**)&w2, g_w2);

    const int SMEM = 65536;
    cudaFuncSetAttribute(gemm_mma<false, false, false>,
                         cudaFuncAttributeMaxDynamicSharedMemorySize, SMEM);
    cudaFuncSetAttribute(gemm_mma<false, true, false>,
                         cudaFuncAttributeMaxDynamicSharedMemorySize, SMEM);
    cudaFuncSetAttribute(gemm_mma<true, false, true>,
                         cudaFuncAttributeMaxDynamicSharedMemorySize, SMEM);

    // Weight splits (every call; weights may change between calls)
    split_w_kernel<<<1024, 256>>>(Wq, wq, DMODEL, (long)DMODEL * DMODEL / 4);
    split_w_kernel<<<1024, 256>>>(Wk, wk, DMODEL, (long)DMODEL * DMODEL / 4);
    split_w_kernel<<<1024, 256>>>(Wv, wv, DMODEL, (long)DMODEL * DMODEL / 4);
    split_w_kernel<<<1024, 256>>>(Wpost, wpost, DMODEL, (long)DMODEL * DMODEL / 4);
    split_w_kernel<<<4096, 256>>>(W1, w1, DMODEL, (long)HID * DMODEL / 4);
    split_w_kernel<<<4096, 256>>>(W2, w2, HID, (long)DMODEL * HID / 4);

    rmsnorm_split_kernel<<<MTOK, 256>>>(inputs, rmsscale, xn_s);

    dim3 g8(8, 64), g32(32, 64);
    gemm_mma<false, false, false><<<g8, 256, SMEM>>>(xn_s, wq, bq, nullptr, q, nullptr, DMODEL, KP1);
    gemm_mma<false, false, false><<<g8, 256, SMEM>>>(xn_s, wk, bk, nullptr, k, nullptr, DMODEL, KP1);
    gemm_mma<false, false, false><<<g8, 256, SMEM>>>(xn_s, wv, bv, nullptr, v, nullptr, DMODEL, KP1);

    attention_kernel<<<dim3(32, 64), 256>>>(q, k, v, mask, pds, attn_s);

    gemm_mma<false, true, false><<<g8, 256, SMEM>>>(attn_s, wpost, bpost, inputs, h, nullptr, DMODEL, KP1);
    layernorm_split_kernel<<<MTOK, 256>>>(h, ln_scale, ln_bias, y_s);
    gemm_mma<true, false, true><<<g32, 256, SMEM>>>(y_s, w1, b1, nullptr, nullptr, hid_s, HID, KP1);
    gemm_mma<false, true, false><<<g8, 256, SMEM>>>(hid_s, w2, b2, h, out, nullptr, DMODEL, KP2);
}